// round 1
// baseline (speedup 1.0000x reference)
#include <cuda_runtime.h>

#define NN   100000
#define DD   64
#define INV  128
#define NC   40
#define NE   1600000
#define NLAY 4

// ---- scratch (device globals: no allocations allowed) ----
__device__ __align__(128) float g_h[NN * DD];
__device__ __align__(128) float g_agg[NN * DD];
__device__ __align__(128) float g_hc[NN * DD];
__device__ float g_norm_src[NN];
__device__ float g_norm_dst[NN];
__device__ float g_stats[2 * DD];   // [0:64) sum, [64:128) sumsq
__device__ float g_scale[DD];
__device__ float g_shift[DD];

// ---------------------------------------------------------------------------
__global__ void zero_deg_kernel() {
    int i = blockIdx.x * blockDim.x + threadIdx.x;
    if (i < NN) { g_norm_src[i] = 0.f; g_norm_dst[i] = 0.f; }
}

__global__ void deg_kernel(const int* __restrict__ src, const int* __restrict__ dst) {
    int i = blockIdx.x * blockDim.x + threadIdx.x;
    if (i < NE) {
        atomicAdd(&g_norm_src[src[i]], 1.f);
        atomicAdd(&g_norm_dst[dst[i]], 1.f);
    }
}

__global__ void norm_kernel() {
    int i = blockIdx.x * blockDim.x + threadIdx.x;
    if (i < NN) {
        g_norm_src[i] = rsqrtf(fmaxf(g_norm_src[i], 1.f));
        g_norm_dst[i] = rsqrtf(fmaxf(g_norm_dst[i], 1.f));
    }
}

// ---------------------------------------------------------------------------
// h = V @ W_in + b_in   (100000x128 @ 128x64)
__global__ void input_gemm_kernel(const float* __restrict__ V,
                                  const float* __restrict__ W,
                                  const float* __restrict__ b) {
    __shared__ float Ws[INV * DD];      // 32 KB
    __shared__ float vr[4][INV];        // 2 KB
    int tid = threadIdx.x;              // 256 threads: 4 nodes x 64 feats
    for (int i = tid; i < INV * DD; i += 256) Ws[i] = W[i];
    int local = tid >> 6;
    int f = tid & 63;
    int n = blockIdx.x * 4 + local;     // NN divisible by 4
    vr[local][f]      = V[(size_t)n * INV + f];
    vr[local][DD + f] = V[(size_t)n * INV + DD + f];
    __syncthreads();
    float acc = b[f];
#pragma unroll
    for (int k = 0; k < INV; k++) acc += vr[local][k] * Ws[k * DD + f];
    g_h[(size_t)n * DD + f] = acc;
}

// ---------------------------------------------------------------------------
__global__ void zero_agg_stats_kernel() {
    int i = blockIdx.x * blockDim.x + threadIdx.x;
    if (i < NN * (DD / 4)) {
        ((float4*)g_agg)[i] = make_float4(0.f, 0.f, 0.f, 0.f);
    }
    if (i < 2 * DD) g_stats[i] = 0.f;
}

// agg[dst] += h[src] * norm_src[src]   — 16 lanes per edge, vectorized REDG
__global__ void edge_kernel(const int* __restrict__ src, const int* __restrict__ dst) {
    unsigned t = blockIdx.x * 256u + threadIdx.x;
    unsigned e = t >> 4;
    int lane16 = t & 15;
    if (e >= NE) return;
    int s = src[e];
    int d = dst[e];
    float nsv = g_norm_src[s];
    float4 v = *reinterpret_cast<const float4*>(g_h + (size_t)s * DD + lane16 * 4);
    float* ap = g_agg + (size_t)d * DD + lane16 * 4;
    asm volatile("red.global.add.v4.f32 [%0], {%1, %2, %3, %4};"
                 :: "l"(ap), "f"(v.x * nsv), "f"(v.y * nsv),
                    "f"(v.z * nsv), "f"(v.w * nsv)
                 : "memory");
}

// ---------------------------------------------------------------------------
// hc = (agg * norm_dst) @ W + b, plus per-feature sum / sumsq partials.
#define GB_NODES 8
__global__ void gemm_bn_kernel(const float* __restrict__ W,
                               const float* __restrict__ bias) {
    __shared__ float Ws[DD * DD];           // 16 KB
    __shared__ float red[GB_NODES][DD];     // 2 KB (A rows, then reductions)
    int tid = threadIdx.x;                  // 512 threads = 8 nodes x 64 feats
    for (int i = tid; i < DD * DD; i += 512) Ws[i] = W[i];
    int local = tid >> 6;
    int f = tid & 63;
    float bf = bias[f];
    float accS = 0.f, accQ = 0.f;
    const int ngroups = (NN + GB_NODES - 1) / GB_NODES;   // 12500
    for (int g = blockIdx.x; g < ngroups; g += gridDim.x) {
        int n = g * GB_NODES + local;
        bool valid = (n < NN);
        __syncthreads();
        red[local][f] = valid ? g_agg[(size_t)n * DD + f] : 0.f;
        __syncthreads();
        float acc = 0.f;
#pragma unroll
        for (int k = 0; k < DD; k++) acc += red[local][k] * Ws[k * DD + f];
        float v = 0.f;
        if (valid) {
            v = acc * g_norm_dst[n] + bf;
            g_hc[(size_t)n * DD + f] = v;
        }
        accS += v;
        accQ += v * v;
    }
    // block reduction over 'local' per feature, then one atomic per feature
    __syncthreads();
    red[local][f] = accS;
    __syncthreads();
    if (local < 4) red[local][f] += red[local + 4][f];
    __syncthreads();
    if (local < 2) red[local][f] += red[local + 2][f];
    __syncthreads();
    if (local == 0) atomicAdd(&g_stats[f], red[0][f] + red[1][f]);
    __syncthreads();
    red[local][f] = accQ;
    __syncthreads();
    if (local < 4) red[local][f] += red[local + 4][f];
    __syncthreads();
    if (local < 2) red[local][f] += red[local + 2][f];
    __syncthreads();
    if (local == 0) atomicAdd(&g_stats[DD + f], red[0][f] + red[1][f]);
}

__global__ void bn_finalize_kernel(const float* __restrict__ gamma,
                                   const float* __restrict__ beta) {
    int f = threadIdx.x;  // 64 threads
    float mean = g_stats[f] * (1.f / NN);
    float ex2  = g_stats[DD + f] * (1.f / NN);
    float var  = ex2 - mean * mean;
    float inv  = rsqrtf(var + 1e-5f);
    float sc   = gamma[f] * inv;
    g_scale[f] = sc;
    g_shift[f] = beta[f] - mean * sc;
}

// h = leakyrelu(hc*scale + shift) + h
__global__ void bn_apply_kernel() {
    int i = blockIdx.x * blockDim.x + threadIdx.x;
    if (i >= NN * (DD / 4)) return;
    int f0 = (i & 15) * 4;
    float4 c  = ((const float4*)g_hc)[i];
    float4 h4 = ((float4*)g_h)[i];
    float v;
    v = c.x * g_scale[f0 + 0] + g_shift[f0 + 0]; h4.x += (v >= 0.f) ? v : 0.2f * v;
    v = c.y * g_scale[f0 + 1] + g_shift[f0 + 1]; h4.y += (v >= 0.f) ? v : 0.2f * v;
    v = c.z * g_scale[f0 + 2] + g_shift[f0 + 2]; h4.z += (v >= 0.f) ? v : 0.2f * v;
    v = c.w * g_scale[f0 + 3] + g_shift[f0 + 3]; h4.w += (v >= 0.f) ? v : 0.2f * v;
    ((float4*)g_h)[i] = h4;
}

// ---------------------------------------------------------------------------
// logits = h @ W_out + b_out, then log_softmax per row. One warp per node.
__global__ void out_kernel(const float* __restrict__ W,
                           const float* __restrict__ b,
                           float* __restrict__ out) {
    __shared__ float Ws[DD * NC];   // 10 KB
    __shared__ float bs[NC];
    int tid = threadIdx.x;          // 256 threads = 8 warps
    for (int i = tid; i < DD * NC; i += 256) Ws[i] = W[i];
    if (tid < NC) bs[tid] = b[tid];
    __syncthreads();
    int warp = tid >> 5, lane = tid & 31;
    int n = blockIdx.x * 8 + warp;  // NN divisible by 8
    if (n >= NN) return;
    int c0 = lane, c1 = lane + 32;
    bool has1 = (c1 < NC);
    float acc0 = bs[c0];
    float acc1 = has1 ? bs[c1] : 0.f;
    const float* hrow = g_h + (size_t)n * DD;
#pragma unroll
    for (int k = 0; k < DD; k++) {
        float hv = hrow[k];
        acc0 += hv * Ws[k * NC + c0];
        if (has1) acc1 += hv * Ws[k * NC + c1];
    }
    float m = has1 ? fmaxf(acc0, acc1) : acc0;
#pragma unroll
    for (int off = 16; off; off >>= 1) m = fmaxf(m, __shfl_xor_sync(0xffffffffu, m, off));
    float e = expf(acc0 - m) + (has1 ? expf(acc1 - m) : 0.f);
#pragma unroll
    for (int off = 16; off; off >>= 1) e += __shfl_xor_sync(0xffffffffu, e, off);
    float ls = m + logf(e);
    out[(size_t)n * NC + c0] = acc0 - ls;
    if (has1) out[(size_t)n * NC + c1] = acc1 - ls;
}

// ---------------------------------------------------------------------------
extern "C" void kernel_launch(void* const* d_in, const int* in_sizes, int n_in,
                              void* d_out, int out_size) {
    const float* V     = (const float*)d_in[0];
    const int*   src   = (const int*)d_in[1];
    const int*   dst   = (const int*)d_in[2];
    const float* W_in  = (const float*)d_in[3];
    const float* b_in  = (const float*)d_in[4];
    const float* W_l   = (const float*)d_in[5];
    const float* b_l   = (const float*)d_in[6];
    const float* gamma = (const float*)d_in[7];
    const float* beta  = (const float*)d_in[8];
    const float* W_out = (const float*)d_in[9];
    const float* b_out = (const float*)d_in[10];
    float* out = (float*)d_out;

    zero_deg_kernel<<<(NN + 255) / 256, 256>>>();
    deg_kernel<<<(NE + 255) / 256, 256>>>(src, dst);
    norm_kernel<<<(NN + 255) / 256, 256>>>();
    input_gemm_kernel<<<NN / 4, 256>>>(V, W_in, b_in);

    for (int l = 0; l < NLAY; l++) {
        zero_agg_stats_kernel<<<(NN * (DD / 4) + 255) / 256, 256>>>();
        edge_kernel<<<(NE * 16) / 256, 256>>>(src, dst);
        gemm_bn_kernel<<<1536, 512>>>(W_l + (size_t)l * DD * DD, b_l + (size_t)l * DD);
        bn_finalize_kernel<<<1, 64>>>(gamma + (size_t)l * DD, beta + (size_t)l * DD);
        bn_apply_kernel<<<(NN * (DD / 4) + 255) / 256, 256>>>();
    }

    out_kernel<<<NN / 8, 256>>>(W_out, b_out, out);
}

// round 2
// speedup vs baseline: 1.6396x; 1.6396x over previous
#include <cuda_runtime.h>

#define NN   100000
#define DD   64
#define INV  128
#define NC   40
#define NE   1600000
#define NLAY 4
#define ASW  21          // padded As row stride (floats)
#define NSB  391         // scan blocks: ceil(NN/256)

// ---- scratch (device globals: no allocations allowed) ----
__device__ __align__(128) float g_h[NN * DD];
__device__ __align__(128) float g_hs[NN * DD];    // h * norm_src (pre-scaled)
__device__ __align__(128) float g_agg[NN * DD];
__device__ __align__(128) float g_hc[NN * DD];
__device__ float g_norm_src[NN];
__device__ float g_norm_dst[NN];
__device__ int   g_deg_out[NN];
__device__ int   g_row_ptr[NN + 1];
__device__ int   g_cursor[NN];
__device__ int   g_col[NE];
__device__ int   g_blocksum[512];
__device__ float g_stats[2 * DD];

// ---------------------------------------------------------------------------
__global__ void init_kernel() {
    int i = blockIdx.x * 256 + threadIdx.x;
    if (i < NN) { g_deg_out[i] = 0; g_cursor[i] = 0; }
}

__global__ void deg_kernel(const int* __restrict__ src, const int* __restrict__ dst) {
    int i = blockIdx.x * 256 + threadIdx.x;
    if (i < NE) {
        atomicAdd(&g_deg_out[src[i]], 1);
        atomicAdd(&g_cursor[dst[i]], 1);     // g_cursor = in-degree (temp)
    }
}

// scan pass A: per-block sums of in-degree
__global__ void scan_a_kernel() {
    __shared__ int s[256];
    int t = threadIdx.x;
    int i = blockIdx.x * 256 + t;
    s[t] = (i < NN) ? g_cursor[i] : 0;
    __syncthreads();
    for (int off = 128; off >= 1; off >>= 1) {
        if (t < off) s[t] += s[t + off];
        __syncthreads();
    }
    if (t == 0) g_blocksum[blockIdx.x] = s[0];
}

// scan pass B: exclusive scan of block sums (single block)
__global__ void scan_b_kernel() {
    __shared__ int s[512];
    int t = threadIdx.x;
    int d = (t < NSB) ? g_blocksum[t] : 0;
    s[t] = d;
    __syncthreads();
    for (int off = 1; off < 512; off <<= 1) {
        int v = (t >= off) ? s[t - off] : 0;
        __syncthreads();
        s[t] += v;
        __syncthreads();
    }
    if (t < NSB) g_blocksum[t] = s[t] - d;   // exclusive
}

// scan pass C: full exclusive scan -> row_ptr/cursor; compute norms
__global__ void scan_c_kernel() {
    __shared__ int s[256];
    int t = threadIdx.x;
    int i = blockIdx.x * 256 + t;
    int d = (i < NN) ? g_cursor[i] : 0;
    s[t] = d;
    __syncthreads();
    for (int off = 1; off < 256; off <<= 1) {
        int v = (t >= off) ? s[t - off] : 0;
        __syncthreads();
        s[t] += v;
        __syncthreads();
    }
    if (i < NN) {
        int start = g_blocksum[blockIdx.x] + s[t] - d;
        g_row_ptr[i] = start;
        g_cursor[i]  = start;
        g_norm_dst[i] = rsqrtf(fmaxf((float)d, 1.f));
        g_norm_src[i] = rsqrtf(fmaxf((float)g_deg_out[i], 1.f));
    }
    if (i == 0) g_row_ptr[NN] = NE;
}

__global__ void fill_kernel(const int* __restrict__ src, const int* __restrict__ dst) {
    int i = blockIdx.x * 256 + threadIdx.x;
    if (i < NE) {
        int pos = atomicAdd(&g_cursor[dst[i]], 1);
        g_col[pos] = src[i];
    }
}

// ---------------------------------------------------------------------------
// h = V @ W_in + b_in ; g_hs = h * norm_src.  Register-tiled: block = 128x64,
// 256 threads, each thread 8 nodes x 4 feats.
__global__ void __launch_bounds__(256) input_gemm_kernel(
        const float* __restrict__ V, const float* __restrict__ W,
        const float* __restrict__ b) {
    __shared__ float Ws[INV * DD];        // 32 KB
    __shared__ float As[128 * ASW];       // 10.5 KB
    int tid = threadIdx.x;
    int node0 = blockIdx.x * 128;
    for (int q = tid; q < INV * DD / 4; q += 256)
        ((float4*)Ws)[q] = ((const float4*)W)[q];
    int tx = tid & 15, ty = tid >> 4;
    float acc[8][4] = {};
    for (int kb = 0; kb < INV; kb += 16) {
        __syncthreads();
#pragma unroll
        for (int u = 0; u < 2; u++) {
            int q = tid * 2 + u;
            int row = q >> 2, kc = q & 3;
            int n = node0 + row;
            float4 av = (n < NN)
                ? *(const float4*)&V[(size_t)n * INV + kb + kc * 4]
                : make_float4(0.f, 0.f, 0.f, 0.f);
            float* p = &As[row * ASW + kc * 4];
            p[0] = av.x; p[1] = av.y; p[2] = av.z; p[3] = av.w;
        }
        __syncthreads();
#pragma unroll
        for (int k = 0; k < 16; k++) {
            float4 w4 = *(const float4*)&Ws[(kb + k) * DD + tx * 4];
#pragma unroll
            for (int i = 0; i < 8; i++) {
                float a = As[(ty * 8 + i) * ASW + k];
                acc[i][0] += a * w4.x; acc[i][1] += a * w4.y;
                acc[i][2] += a * w4.z; acc[i][3] += a * w4.w;
            }
        }
    }
    float4 bv = *(const float4*)&b[tx * 4];
#pragma unroll
    for (int i = 0; i < 8; i++) {
        int n = node0 + ty * 8 + i;
        if (n < NN) {
            float ns = g_norm_src[n];
            float4 h4;
            h4.x = acc[i][0] + bv.x; h4.y = acc[i][1] + bv.y;
            h4.z = acc[i][2] + bv.z; h4.w = acc[i][3] + bv.w;
            *(float4*)&g_h[(size_t)n * DD + tx * 4] = h4;
            float4 s4 = make_float4(h4.x * ns, h4.y * ns, h4.z * ns, h4.w * ns);
            *(float4*)&g_hs[(size_t)n * DD + tx * 4] = s4;
        }
    }
}

// ---------------------------------------------------------------------------
// CSR gather segment-sum: agg[n] = norm_dst[n] * sum_{e in row n} g_hs[col[e]]
// 64 threads per node (thread = feature), 4 nodes per block.
__global__ void gather_kernel() {
    int tid = threadIdx.x;
    if (blockIdx.x == 0 && tid < 2 * DD) g_stats[tid] = 0.f;   // zero BN stats
    int node = blockIdx.x * 4 + (tid >> 6);
    int f = tid & 63;
    int e   = g_row_ptr[node];
    int end = g_row_ptr[node + 1];
    float acc = 0.f;
    for (; e + 4 <= end; e += 4) {
        int s0 = g_col[e], s1 = g_col[e + 1], s2 = g_col[e + 2], s3 = g_col[e + 3];
        float a0 = g_hs[(size_t)s0 * DD + f];
        float a1 = g_hs[(size_t)s1 * DD + f];
        float a2 = g_hs[(size_t)s2 * DD + f];
        float a3 = g_hs[(size_t)s3 * DD + f];
        acc += (a0 + a1) + (a2 + a3);
    }
    for (; e < end; e++) acc += g_hs[(size_t)g_col[e] * DD + f];
    g_agg[(size_t)node * DD + f] = acc * g_norm_dst[node];
}

// ---------------------------------------------------------------------------
// hc = agg @ W + b (norm_dst already applied); accumulate BN sum/sumsq.
__global__ void __launch_bounds__(256) gemm_bn_kernel(
        const float* __restrict__ W, const float* __restrict__ bias) {
    __shared__ float Ws[DD * DD];         // 16 KB
    __shared__ float As[128 * ASW];       // 10.5 KB
    __shared__ float sred[16][128];       // 8 KB: [ty][sum(64) | sumsq(64)]
    int tid = threadIdx.x;
    int node0 = blockIdx.x * 128;
    for (int q = tid; q < DD * DD / 4; q += 256)
        ((float4*)Ws)[q] = ((const float4*)W)[q];
    int tx = tid & 15, ty = tid >> 4;
    float acc[8][4] = {};
    for (int kb = 0; kb < DD; kb += 16) {
        __syncthreads();
#pragma unroll
        for (int u = 0; u < 2; u++) {
            int q = tid * 2 + u;
            int row = q >> 2, kc = q & 3;
            int n = node0 + row;
            float4 av = (n < NN)
                ? *(const float4*)&g_agg[(size_t)n * DD + kb + kc * 4]
                : make_float4(0.f, 0.f, 0.f, 0.f);
            float* p = &As[row * ASW + kc * 4];
            p[0] = av.x; p[1] = av.y; p[2] = av.z; p[3] = av.w;
        }
        __syncthreads();
#pragma unroll
        for (int k = 0; k < 16; k++) {
            float4 w4 = *(const float4*)&Ws[(kb + k) * DD + tx * 4];
#pragma unroll
            for (int i = 0; i < 8; i++) {
                float a = As[(ty * 8 + i) * ASW + k];
                acc[i][0] += a * w4.x; acc[i][1] += a * w4.y;
                acc[i][2] += a * w4.z; acc[i][3] += a * w4.w;
            }
        }
    }
    float4 bv = *(const float4*)&bias[tx * 4];
    float sS[4] = {}, sQ[4] = {};
#pragma unroll
    for (int i = 0; i < 8; i++) {
        int n = node0 + ty * 8 + i;
        if (n < NN) {
            float4 v;
            v.x = acc[i][0] + bv.x; v.y = acc[i][1] + bv.y;
            v.z = acc[i][2] + bv.z; v.w = acc[i][3] + bv.w;
            *(float4*)&g_hc[(size_t)n * DD + tx * 4] = v;
            sS[0] += v.x; sS[1] += v.y; sS[2] += v.z; sS[3] += v.w;
            sQ[0] += v.x * v.x; sQ[1] += v.y * v.y;
            sQ[2] += v.z * v.z; sQ[3] += v.w * v.w;
        }
    }
    __syncthreads();
#pragma unroll
    for (int j = 0; j < 4; j++) {
        sred[ty][tx * 4 + j]      = sS[j];
        sred[ty][64 + tx * 4 + j] = sQ[j];
    }
    __syncthreads();
    for (int off = 8; off >= 1; off >>= 1) {
        if (ty < off) {
#pragma unroll
            for (int j = 0; j < 4; j++) {
                sred[ty][tx * 4 + j]      += sred[ty + off][tx * 4 + j];
                sred[ty][64 + tx * 4 + j] += sred[ty + off][64 + tx * 4 + j];
            }
        }
        __syncthreads();
    }
    if (ty == 0) {
#pragma unroll
        for (int j = 0; j < 4; j++) {
            atomicAdd(&g_stats[tx * 4 + j],      sred[0][tx * 4 + j]);
            atomicAdd(&g_stats[DD + tx * 4 + j], sred[0][64 + tx * 4 + j]);
        }
    }
}

// ---------------------------------------------------------------------------
// finalize BN (per-block, from g_stats) + apply + leakyrelu + residual;
// also write g_hs = h * norm_src for next layer.
__global__ void bn_apply_kernel(const float* __restrict__ gamma,
                                const float* __restrict__ beta) {
    __shared__ float sc[DD], sh[DD];
    int tid = threadIdx.x;
    if (tid < DD) {
        float mean = g_stats[tid] * (1.f / NN);
        float ex2  = g_stats[DD + tid] * (1.f / NN);
        float inv  = rsqrtf(ex2 - mean * mean + 1e-5f);
        float s    = gamma[tid] * inv;
        sc[tid] = s;
        sh[tid] = beta[tid] - mean * s;
    }
    __syncthreads();
    int i = blockIdx.x * 256 + tid;          // over NN*16 float4s
    if (i >= NN * (DD / 4)) return;
    int n = i >> 4;
    int f0 = (i & 15) * 4;
    float4 c  = ((const float4*)g_hc)[i];
    float4 h4 = ((const float4*)g_h)[i];
    float ns = g_norm_src[n];
    float v;
    v = c.x * sc[f0 + 0] + sh[f0 + 0]; h4.x += (v >= 0.f) ? v : 0.2f * v;
    v = c.y * sc[f0 + 1] + sh[f0 + 1]; h4.y += (v >= 0.f) ? v : 0.2f * v;
    v = c.z * sc[f0 + 2] + sh[f0 + 2]; h4.z += (v >= 0.f) ? v : 0.2f * v;
    v = c.w * sc[f0 + 3] + sh[f0 + 3]; h4.w += (v >= 0.f) ? v : 0.2f * v;
    ((float4*)g_h)[i] = h4;
    float4 s4 = make_float4(h4.x * ns, h4.y * ns, h4.z * ns, h4.w * ns);
    ((float4*)g_hs)[i] = s4;
}

// ---------------------------------------------------------------------------
// logits = h @ W_out + b_out, then log_softmax per row. One warp per node.
__global__ void out_kernel(const float* __restrict__ W,
                           const float* __restrict__ b,
                           float* __restrict__ out) {
    __shared__ float Ws[DD * NC];   // 10 KB
    __shared__ float bs[NC];
    int tid = threadIdx.x;          // 256 threads = 8 warps
    for (int i = tid; i < DD * NC; i += 256) Ws[i] = W[i];
    if (tid < NC) bs[tid] = b[tid];
    __syncthreads();
    int warp = tid >> 5, lane = tid & 31;
    int n = blockIdx.x * 8 + warp;  // NN divisible by 8
    if (n >= NN) return;
    int c0 = lane, c1 = lane + 32;
    bool has1 = (c1 < NC);
    float acc0 = bs[c0];
    float acc1 = has1 ? bs[c1] : 0.f;
    const float* hrow = g_h + (size_t)n * DD;
#pragma unroll
    for (int k = 0; k < DD; k++) {
        float hv = hrow[k];
        acc0 += hv * Ws[k * NC + c0];
        if (has1) acc1 += hv * Ws[k * NC + c1];
    }
    float m = has1 ? fmaxf(acc0, acc1) : acc0;
#pragma unroll
    for (int off = 16; off; off >>= 1) m = fmaxf(m, __shfl_xor_sync(0xffffffffu, m, off));
    float e = expf(acc0 - m) + (has1 ? expf(acc1 - m) : 0.f);
#pragma unroll
    for (int off = 16; off; off >>= 1) e += __shfl_xor_sync(0xffffffffu, e, off);
    float ls = m + logf(e);
    out[(size_t)n * NC + c0] = acc0 - ls;
    if (has1) out[(size_t)n * NC + c1] = acc1 - ls;
}

// ---------------------------------------------------------------------------
extern "C" void kernel_launch(void* const* d_in, const int* in_sizes, int n_in,
                              void* d_out, int out_size) {
    const float* V     = (const float*)d_in[0];
    const int*   src   = (const int*)d_in[1];
    const int*   dst   = (const int*)d_in[2];
    const float* W_in  = (const float*)d_in[3];
    const float* b_in  = (const float*)d_in[4];
    const float* W_l   = (const float*)d_in[5];
    const float* b_l   = (const float*)d_in[6];
    const float* gamma = (const float*)d_in[7];
    const float* beta  = (const float*)d_in[8];
    const float* W_out = (const float*)d_in[9];
    const float* b_out = (const float*)d_in[10];
    float* out = (float*)d_out;

    init_kernel<<<NSB, 256>>>();
    deg_kernel<<<(NE + 255) / 256, 256>>>(src, dst);
    scan_a_kernel<<<NSB, 256>>>();
    scan_b_kernel<<<1, 512>>>();
    scan_c_kernel<<<NSB, 256>>>();
    fill_kernel<<<(NE + 255) / 256, 256>>>(src, dst);

    input_gemm_kernel<<<(NN + 127) / 128, 256>>>(V, W_in, b_in);

    for (int l = 0; l < NLAY; l++) {
        gather_kernel<<<NN / 4, 256>>>();
        gemm_bn_kernel<<<(NN + 127) / 128, 256>>>(W_l + (size_t)l * DD * DD,
                                                  b_l + (size_t)l * DD);
        bn_apply_kernel<<<(NN * (DD / 4) + 255) / 256, 256>>>(
            gamma + (size_t)l * DD, beta + (size_t)l * DD);
    }

    out_kernel<<<NN / 8, 256>>>(W_out, b_out, out);
}

// round 3
// speedup vs baseline: 2.0015x; 1.2208x over previous
#include <cuda_runtime.h>
#include <cuda_fp16.h>

#define NN   100000
#define DD   64
#define INV  128
#define NC   40
#define NE   1600000
#define NLAY 4
#define ASW  21          // padded As row stride (floats)
#define NSB  391         // scan blocks: ceil(NN/256)

// ---- scratch (device globals: no allocations allowed) ----
__device__ __align__(128) float  g_h[NN * DD];
__device__ __align__(128) __half g_hs16[NN * DD];   // (h * norm_src) in fp16
__device__ __align__(128) float  g_agg[NN * DD];
__device__ __align__(128) float  g_hc[NN * DD];
__device__ float g_norm_src[NN];
__device__ float g_norm_dst[NN];
__device__ int   g_deg_out[NN];
__device__ int   g_row_ptr[NN + 1];
__device__ int   g_cursor[NN];
__device__ int   g_col[NE];
__device__ int   g_blocksum[512];
__device__ float g_stats[2 * DD];

// ---------------------------------------------------------------------------
__global__ void init_kernel() {
    int i = blockIdx.x * 256 + threadIdx.x;
    if (i < NN) { g_deg_out[i] = 0; g_cursor[i] = 0; }
}

__global__ void deg_kernel(const int* __restrict__ src, const int* __restrict__ dst) {
    int i = blockIdx.x * 256 + threadIdx.x;
    if (i < NE) {
        atomicAdd(&g_deg_out[src[i]], 1);
        atomicAdd(&g_cursor[dst[i]], 1);     // g_cursor = in-degree (temp)
    }
}

// scan pass A: per-block sums of in-degree
__global__ void scan_a_kernel() {
    __shared__ int s[256];
    int t = threadIdx.x;
    int i = blockIdx.x * 256 + t;
    s[t] = (i < NN) ? g_cursor[i] : 0;
    __syncthreads();
    for (int off = 128; off >= 1; off >>= 1) {
        if (t < off) s[t] += s[t + off];
        __syncthreads();
    }
    if (t == 0) g_blocksum[blockIdx.x] = s[0];
}

// scan pass B: exclusive scan of block sums (single block)
__global__ void scan_b_kernel() {
    __shared__ int s[512];
    int t = threadIdx.x;
    int d = (t < NSB) ? g_blocksum[t] : 0;
    s[t] = d;
    __syncthreads();
    for (int off = 1; off < 512; off <<= 1) {
        int v = (t >= off) ? s[t - off] : 0;
        __syncthreads();
        s[t] += v;
        __syncthreads();
    }
    if (t < NSB) g_blocksum[t] = s[t] - d;   // exclusive
}

// scan pass C: full exclusive scan -> row_ptr/cursor; compute norms
__global__ void scan_c_kernel() {
    __shared__ int s[256];
    int t = threadIdx.x;
    int i = blockIdx.x * 256 + t;
    int d = (i < NN) ? g_cursor[i] : 0;
    s[t] = d;
    __syncthreads();
    for (int off = 1; off < 256; off <<= 1) {
        int v = (t >= off) ? s[t - off] : 0;
        __syncthreads();
        s[t] += v;
        __syncthreads();
    }
    if (i < NN) {
        int start = g_blocksum[blockIdx.x] + s[t] - d;
        g_row_ptr[i] = start;
        g_cursor[i]  = start;
        g_norm_dst[i] = rsqrtf(fmaxf((float)d, 1.f));
        g_norm_src[i] = rsqrtf(fmaxf((float)g_deg_out[i], 1.f));
    }
    if (i == 0) g_row_ptr[NN] = NE;
}

__global__ void fill_kernel(const int* __restrict__ src, const int* __restrict__ dst) {
    int i = blockIdx.x * 256 + threadIdx.x;
    if (i < NE) {
        int pos = atomicAdd(&g_cursor[dst[i]], 1);
        g_col[pos] = src[i];
    }
}

// ---------------------------------------------------------------------------
// h = V @ W_in + b_in ; g_hs16 = fp16(h * norm_src).  Register-tiled.
__global__ void __launch_bounds__(256) input_gemm_kernel(
        const float* __restrict__ V, const float* __restrict__ W,
        const float* __restrict__ b) {
    __shared__ float Ws[INV * DD];        // 32 KB
    __shared__ float As[128 * ASW];       // 10.5 KB
    int tid = threadIdx.x;
    int node0 = blockIdx.x * 128;
    for (int q = tid; q < INV * DD / 4; q += 256)
        ((float4*)Ws)[q] = ((const float4*)W)[q];
    int tx = tid & 15, ty = tid >> 4;
    float acc[8][4] = {};
    for (int kb = 0; kb < INV; kb += 16) {
        __syncthreads();
#pragma unroll
        for (int u = 0; u < 2; u++) {
            int q = tid * 2 + u;
            int row = q >> 2, kc = q & 3;
            int n = node0 + row;
            float4 av = (n < NN)
                ? *(const float4*)&V[(size_t)n * INV + kb + kc * 4]
                : make_float4(0.f, 0.f, 0.f, 0.f);
            float* p = &As[row * ASW + kc * 4];
            p[0] = av.x; p[1] = av.y; p[2] = av.z; p[3] = av.w;
        }
        __syncthreads();
#pragma unroll
        for (int k = 0; k < 16; k++) {
            float4 w4 = *(const float4*)&Ws[(kb + k) * DD + tx * 4];
#pragma unroll
            for (int i = 0; i < 8; i++) {
                float a = As[(ty * 8 + i) * ASW + k];
                acc[i][0] += a * w4.x; acc[i][1] += a * w4.y;
                acc[i][2] += a * w4.z; acc[i][3] += a * w4.w;
            }
        }
    }
    float4 bv = *(const float4*)&b[tx * 4];
#pragma unroll
    for (int i = 0; i < 8; i++) {
        int n = node0 + ty * 8 + i;
        if (n < NN) {
            float ns = g_norm_src[n];
            float4 h4;
            h4.x = acc[i][0] + bv.x; h4.y = acc[i][1] + bv.y;
            h4.z = acc[i][2] + bv.z; h4.w = acc[i][3] + bv.w;
            *(float4*)&g_h[(size_t)n * DD + tx * 4] = h4;
            __half2* hp = (__half2*)&g_hs16[(size_t)n * DD + tx * 4];
            hp[0] = __floats2half2_rn(h4.x * ns, h4.y * ns);
            hp[1] = __floats2half2_rn(h4.z * ns, h4.w * ns);
        }
    }
}

// ---------------------------------------------------------------------------
// CSR gather segment-sum from fp16 rows, fp32 accumulation.
// One warp per node: 32 lanes x half2 = full 64-feat row (128B) per edge.
__global__ void __launch_bounds__(256) gather_kernel() {
    int tid = threadIdx.x;
    if (blockIdx.x == 0 && tid < 2 * DD) g_stats[tid] = 0.f;   // zero BN stats
    int warp = tid >> 5, lane = tid & 31;
    int node = blockIdx.x * 8 + warp;            // NN divisible by 8
    int e   = g_row_ptr[node];
    int end = g_row_ptr[node + 1];
    const __half2* __restrict__ hs = (const __half2*)g_hs16;
    float ax = 0.f, ay = 0.f;
    for (; e + 4 <= end; e += 4) {
        int s0 = g_col[e], s1 = g_col[e + 1], s2 = g_col[e + 2], s3 = g_col[e + 3];
        float2 a0 = __half22float2(hs[(size_t)s0 * 32 + lane]);
        float2 a1 = __half22float2(hs[(size_t)s1 * 32 + lane]);
        float2 a2 = __half22float2(hs[(size_t)s2 * 32 + lane]);
        float2 a3 = __half22float2(hs[(size_t)s3 * 32 + lane]);
        ax += (a0.x + a1.x) + (a2.x + a3.x);
        ay += (a0.y + a1.y) + (a2.y + a3.y);
    }
    for (; e < end; e++) {
        float2 a = __half22float2(hs[(size_t)g_col[e] * 32 + lane]);
        ax += a.x; ay += a.y;
    }
    float nd = g_norm_dst[node];
    *(float2*)&g_agg[(size_t)node * DD + lane * 2] = make_float2(ax * nd, ay * nd);
}

// ---------------------------------------------------------------------------
// hc = agg @ W + b (norm_dst already applied); accumulate BN sum/sumsq.
__global__ void __launch_bounds__(256) gemm_bn_kernel(
        const float* __restrict__ W, const float* __restrict__ bias) {
    __shared__ float Ws[DD * DD];         // 16 KB
    __shared__ float As[128 * ASW];       // 10.5 KB
    __shared__ float sred[16][128];       // 8 KB
    int tid = threadIdx.x;
    int node0 = blockIdx.x * 128;
    for (int q = tid; q < DD * DD / 4; q += 256)
        ((float4*)Ws)[q] = ((const float4*)W)[q];
    int tx = tid & 15, ty = tid >> 4;
    float acc[8][4] = {};
    for (int kb = 0; kb < DD; kb += 16) {
        __syncthreads();
#pragma unroll
        for (int u = 0; u < 2; u++) {
            int q = tid * 2 + u;
            int row = q >> 2, kc = q & 3;
            int n = node0 + row;
            float4 av = (n < NN)
                ? *(const float4*)&g_agg[(size_t)n * DD + kb + kc * 4]
                : make_float4(0.f, 0.f, 0.f, 0.f);
            float* p = &As[row * ASW + kc * 4];
            p[0] = av.x; p[1] = av.y; p[2] = av.z; p[3] = av.w;
        }
        __syncthreads();
#pragma unroll
        for (int k = 0; k < 16; k++) {
            float4 w4 = *(const float4*)&Ws[(kb + k) * DD + tx * 4];
#pragma unroll
            for (int i = 0; i < 8; i++) {
                float a = As[(ty * 8 + i) * ASW + k];
                acc[i][0] += a * w4.x; acc[i][1] += a * w4.y;
                acc[i][2] += a * w4.z; acc[i][3] += a * w4.w;
            }
        }
    }
    float4 bv = *(const float4*)&bias[tx * 4];
    float sS[4] = {}, sQ[4] = {};
#pragma unroll
    for (int i = 0; i < 8; i++) {
        int n = node0 + ty * 8 + i;
        if (n < NN) {
            float4 v;
            v.x = acc[i][0] + bv.x; v.y = acc[i][1] + bv.y;
            v.z = acc[i][2] + bv.z; v.w = acc[i][3] + bv.w;
            *(float4*)&g_hc[(size_t)n * DD + tx * 4] = v;
            sS[0] += v.x; sS[1] += v.y; sS[2] += v.z; sS[3] += v.w;
            sQ[0] += v.x * v.x; sQ[1] += v.y * v.y;
            sQ[2] += v.z * v.z; sQ[3] += v.w * v.w;
        }
    }
    __syncthreads();
#pragma unroll
    for (int j = 0; j < 4; j++) {
        sred[ty][tx * 4 + j]      = sS[j];
        sred[ty][64 + tx * 4 + j] = sQ[j];
    }
    __syncthreads();
    for (int off = 8; off >= 1; off >>= 1) {
        if (ty < off) {
#pragma unroll
            for (int j = 0; j < 4; j++) {
                sred[ty][tx * 4 + j]      += sred[ty + off][tx * 4 + j];
                sred[ty][64 + tx * 4 + j] += sred[ty + off][64 + tx * 4 + j];
            }
        }
        __syncthreads();
    }
    if (ty == 0) {
#pragma unroll
        for (int j = 0; j < 4; j++) {
            atomicAdd(&g_stats[tx * 4 + j],      sred[0][tx * 4 + j]);
            atomicAdd(&g_stats[DD + tx * 4 + j], sred[0][64 + tx * 4 + j]);
        }
    }
}

// ---------------------------------------------------------------------------
// finalize BN + apply + leakyrelu + residual; write g_hs16 for next layer.
__global__ void bn_apply_kernel(const float* __restrict__ gamma,
                                const float* __restrict__ beta) {
    __shared__ float sc[DD], sh[DD];
    int tid = threadIdx.x;
    if (tid < DD) {
        float mean = g_stats[tid] * (1.f / NN);
        float ex2  = g_stats[DD + tid] * (1.f / NN);
        float inv  = rsqrtf(ex2 - mean * mean + 1e-5f);
        float s    = gamma[tid] * inv;
        sc[tid] = s;
        sh[tid] = beta[tid] - mean * s;
    }
    __syncthreads();
    int i = blockIdx.x * 256 + tid;          // over NN*16 float4s
    if (i >= NN * (DD / 4)) return;
    int n = i >> 4;
    int f0 = (i & 15) * 4;
    float4 c  = ((const float4*)g_hc)[i];
    float4 h4 = ((const float4*)g_h)[i];
    float ns = g_norm_src[n];
    float v;
    v = c.x * sc[f0 + 0] + sh[f0 + 0]; h4.x += (v >= 0.f) ? v : 0.2f * v;
    v = c.y * sc[f0 + 1] + sh[f0 + 1]; h4.y += (v >= 0.f) ? v : 0.2f * v;
    v = c.z * sc[f0 + 2] + sh[f0 + 2]; h4.z += (v >= 0.f) ? v : 0.2f * v;
    v = c.w * sc[f0 + 3] + sh[f0 + 3]; h4.w += (v >= 0.f) ? v : 0.2f * v;
    ((float4*)g_h)[i] = h4;
    __half2* hp = (__half2*)&g_hs16[(size_t)i * 4];
    hp[0] = __floats2half2_rn(h4.x * ns, h4.y * ns);
    hp[1] = __floats2half2_rn(h4.z * ns, h4.w * ns);
}

// ---------------------------------------------------------------------------
// logits = h @ W_out + b_out, then log_softmax per row. One warp per node.
__global__ void out_kernel(const float* __restrict__ W,
                           const float* __restrict__ b,
                           float* __restrict__ out) {
    __shared__ float Ws[DD * NC];   // 10 KB
    __shared__ float bs[NC];
    int tid = threadIdx.x;          // 256 threads = 8 warps
    for (int i = tid; i < DD * NC; i += 256) Ws[i] = W[i];
    if (tid < NC) bs[tid] = b[tid];
    __syncthreads();
    int warp = tid >> 5, lane = tid & 31;
    int n = blockIdx.x * 8 + warp;  // NN divisible by 8
    if (n >= NN) return;
    int c0 = lane, c1 = lane + 32;
    bool has1 = (c1 < NC);
    float acc0 = bs[c0];
    float acc1 = has1 ? bs[c1] : 0.f;
    const float* hrow = g_h + (size_t)n * DD;
#pragma unroll
    for (int k = 0; k < DD; k++) {
        float hv = hrow[k];
        acc0 += hv * Ws[k * NC + c0];
        if (has1) acc1 += hv * Ws[k * NC + c1];
    }
    float m = has1 ? fmaxf(acc0, acc1) : acc0;
#pragma unroll
    for (int off = 16; off; off >>= 1) m = fmaxf(m, __shfl_xor_sync(0xffffffffu, m, off));
    float e = expf(acc0 - m) + (has1 ? expf(acc1 - m) : 0.f);
#pragma unroll
    for (int off = 16; off; off >>= 1) e += __shfl_xor_sync(0xffffffffu, e, off);
    float ls = m + logf(e);
    out[(size_t)n * NC + c0] = acc0 - ls;
    if (has1) out[(size_t)n * NC + c1] = acc1 - ls;
}

// ---------------------------------------------------------------------------
extern "C" void kernel_launch(void* const* d_in, const int* in_sizes, int n_in,
                              void* d_out, int out_size) {
    const float* V     = (const float*)d_in[0];
    const int*   src   = (const int*)d_in[1];
    const int*   dst   = (const int*)d_in[2];
    const float* W_in  = (const float*)d_in[3];
    const float* b_in  = (const float*)d_in[4];
    const float* W_l   = (const float*)d_in[5];
    const float* b_l   = (const float*)d_in[6];
    const float* gamma = (const float*)d_in[7];
    const float* beta  = (const float*)d_in[8];
    const float* W_out = (const float*)d_in[9];
    const float* b_out = (const float*)d_in[10];
    float* out = (float*)d_out;

    init_kernel<<<NSB, 256>>>();
    deg_kernel<<<(NE + 255) / 256, 256>>>(src, dst);
    scan_a_kernel<<<NSB, 256>>>();
    scan_b_kernel<<<1, 512>>>();
    scan_c_kernel<<<NSB, 256>>>();
    fill_kernel<<<(NE + 255) / 256, 256>>>(src, dst);

    input_gemm_kernel<<<(NN + 127) / 128, 256>>>(V, W_in, b_in);

    for (int l = 0; l < NLAY; l++) {
        gather_kernel<<<NN / 8, 256>>>();
        gemm_bn_kernel<<<(NN + 127) / 128, 256>>>(W_l + (size_t)l * DD * DD,
                                                  b_l + (size_t)l * DD);
        bn_apply_kernel<<<(NN * (DD / 4) + 255) / 256, 256>>>(
            gamma + (size_t)l * DD, beta + (size_t)l * DD);
    }

    out_kernel<<<NN / 8, 256>>>(W_out, b_out, out);
}